// round 2
// baseline (speedup 1.0000x reference)
#include <cuda_runtime.h>
#include <math.h>

// Problem constants (fixed shapes)
#define NPTS   16384
#define MPTS   4096          // NPTS / STRIDE(4)
#define KNN    16
#define DIN    64
#define DF     67            // 3 + DIN
#define DOUT   128
#define NCHUNK 8
#define CHSZ   (NPTS / NCHUNK)   // 2048
#define FPS_T  1024
#define PPT    (NPTS / FPS_T)    // 16

// ---------------- scratch (static device allocations; no cudaMalloc) -------
__device__ float g_cand_d[MPTS * NCHUNK * KNN];
__device__ int   g_cand_i[MPTS * NCHUNK * KNN];
__device__ float g_feat[MPTS * DF];
__device__ float g_h[MPTS * DOUT];
__device__ float g_scale[DOUT];
__device__ float g_shift[DOUT];

// ---------------------------------------------------------------------------
// 1) Furthest point sampling — single persistent block, coords in smem,
//    per-point running min-dists in registers. Exact (non-FMA) arithmetic to
//    match the reference's ((dx^2+dy^2)+dz^2) rounding; argmax tie-break =
//    smallest index (jnp.argmax first-occurrence).
// ---------------------------------------------------------------------------
__global__ __launch_bounds__(FPS_T, 1)
void fps_kernel(const float* __restrict__ p, float* __restrict__ np_out)
{
    extern __shared__ float sm[];
    float* sx = sm;
    float* sy = sm + NPTS;
    float* sz = sm + 2 * NPTS;
    __shared__ float red_v[32];
    __shared__ int   red_i[32];
    __shared__ float cur[3];

    const int tid  = threadIdx.x;
    const int lane = tid & 31;
    const int wid  = tid >> 5;

    for (int i = tid; i < NPTS; i += FPS_T) {
        sx[i] = p[3 * i + 0];
        sy[i] = p[3 * i + 1];
        sz[i] = p[3 * i + 2];
    }

    float d[PPT];
#pragma unroll
    for (int k = 0; k < PPT; k++) d[k] = __int_as_float(0x7f800000); // +inf

    if (tid == 0) {
        cur[0] = p[0]; cur[1] = p[1]; cur[2] = p[2];
        np_out[0] = p[0]; np_out[1] = p[1]; np_out[2] = p[2];
    }
    __syncthreads();

    for (int it = 1; it < MPTS; it++) {
        const float lx = cur[0], ly = cur[1], lz = cur[2];
        float bestv = -1.0f;   // dists are >= 0
        int   besti = 0;
#pragma unroll
        for (int k = 0; k < PPT; k++) {
            const int idx = tid + (k << 10);
            float dx = __fsub_rn(sx[idx], lx);
            float dy = __fsub_rn(sy[idx], ly);
            float dz = __fsub_rn(sz[idx], lz);
            float s  = __fadd_rn(__fadd_rn(__fmul_rn(dx, dx), __fmul_rn(dy, dy)),
                                 __fmul_rn(dz, dz));
            float dn = fminf(d[k], s);
            d[k] = dn;
            if (dn > bestv) { bestv = dn; besti = idx; } // ascending idx -> first-max
        }
        // warp argmax (smallest index on ties)
#pragma unroll
        for (int off = 16; off > 0; off >>= 1) {
            float ov = __shfl_down_sync(0xffffffffu, bestv, off);
            int   oi = __shfl_down_sync(0xffffffffu, besti, off);
            if (ov > bestv || (ov == bestv && oi < besti)) { bestv = ov; besti = oi; }
        }
        if (lane == 0) { red_v[wid] = bestv; red_i[wid] = besti; }
        __syncthreads();
        if (wid == 0) {
            bestv = red_v[lane];
            besti = red_i[lane];
#pragma unroll
            for (int off = 16; off > 0; off >>= 1) {
                float ov = __shfl_down_sync(0xffffffffu, bestv, off);
                int   oi = __shfl_down_sync(0xffffffffu, besti, off);
                if (ov > bestv || (ov == bestv && oi < besti)) { bestv = ov; besti = oi; }
            }
            if (lane == 0) {
                float wx = sx[besti], wy = sy[besti], wz = sz[besti];
                cur[0] = wx; cur[1] = wy; cur[2] = wz;
                np_out[3 * it + 0] = wx;
                np_out[3 * it + 1] = wy;
                np_out[3 * it + 2] = wz;
            }
        }
        __syncthreads();
    }
}

// ---------------------------------------------------------------------------
// 2) kNN phase A: one thread per (query, chunk). Chunk coords staged in smem;
//    register-resident sorted top-16 with bubble insert.
// ---------------------------------------------------------------------------
__global__ __launch_bounds__(256)
void knn_kernel(const float* __restrict__ p, const float* __restrict__ np)
{
    __shared__ float sx[CHSZ], sy[CHSZ], sz[CHSZ];
    const int c = blockIdx.y;
    const int q = blockIdx.x * blockDim.x + threadIdx.x;

    for (int i = threadIdx.x; i < CHSZ; i += blockDim.x) {
        const int g = c * CHSZ + i;
        sx[i] = p[3 * g + 0];
        sy[i] = p[3 * g + 1];
        sz[i] = p[3 * g + 2];
    }
    __syncthreads();

    const float qx = np[3 * q + 0];
    const float qy = np[3 * q + 1];
    const float qz = np[3 * q + 2];

    float dk[KNN];
    int   ik[KNN];
#pragma unroll
    for (int t = 0; t < KNN; t++) { dk[t] = __int_as_float(0x7f800000); ik[t] = 0; }

    for (int j = 0; j < CHSZ; j++) {
        float dx = qx - sx[j];
        float dy = qy - sy[j];
        float dz = qz - sz[j];
        float d2 = dx * dx + dy * dy + dz * dz;
        if (d2 < dk[KNN - 1]) {
            float cd = d2;
            int   ci = c * CHSZ + j;
#pragma unroll
            for (int t = 0; t < KNN; t++) {
                if (cd < dk[t]) {
                    float td = dk[t]; int ti = ik[t];
                    dk[t] = cd; ik[t] = ci;
                    cd = td; ci = ti;
                }
            }
        }
    }
    const int base = (q * NCHUNK + c) * KNN;
#pragma unroll
    for (int t = 0; t < KNN; t++) {
        g_cand_d[base + t] = dk[t];
        g_cand_i[base + t] = ik[t];
    }
}

// ---------------------------------------------------------------------------
// 3) Merge 8 sorted candidate lists -> top-16 set, then gather neighbors,
//    normalize relative coords by max neighbor norm, and max-pool to 67 dims.
//    One warp per query.
// ---------------------------------------------------------------------------
__global__ __launch_bounds__(128)
void feat_kernel(const float* __restrict__ p, const float* __restrict__ x,
                 const float* __restrict__ np)
{
    const int w    = threadIdx.x >> 5;
    const int lane = threadIdx.x & 31;
    const int q    = blockIdx.x * 4 + w;

    __shared__ int s_nn[4][KNN];

    if (lane == 0) {
        int hpos[NCHUNK];
#pragma unroll
        for (int c = 0; c < NCHUNK; c++) hpos[c] = 0;
        for (int t = 0; t < KNN; t++) {
            float best = __int_as_float(0x7f800000);
            int   bc   = 0;
#pragma unroll
            for (int c = 0; c < NCHUNK; c++) {
                float v = g_cand_d[(q * NCHUNK + c) * KNN + hpos[c]];
                if (v < best) { best = v; bc = c; }
            }
            s_nn[w][t] = g_cand_i[(q * NCHUNK + bc) * KNN + hpos[bc]];
            hpos[bc]++;
        }
    }
    __syncwarp();

    const float qx = np[3 * q + 0];
    const float qy = np[3 * q + 1];
    const float qz = np[3 * q + 2];

    // max neighbor norm (lanes 0..15 compute one norm each)
    float nr = -1.0f;
    if (lane < KNN) {
        int j = s_nn[w][lane];
        float rx = p[3 * j + 0] - qx;
        float ry = p[3 * j + 1] - qy;
        float rz = p[3 * j + 2] - qz;
        nr = sqrtf(rx * rx + ry * ry + rz * rz);
    }
#pragma unroll
    for (int off = 16; off > 0; off >>= 1)
        nr = fmaxf(nr, __shfl_xor_sync(0xffffffffu, nr, off));
    const float den = nr + 1e-8f;

    if (lane < 3) {
        const float qc = (lane == 0) ? qx : (lane == 1) ? qy : qz;
        float mv = -__int_as_float(0x7f800000);
#pragma unroll
        for (int k = 0; k < KNN; k++) {
            int j = s_nn[w][k];
            mv = fmaxf(mv, p[3 * j + lane] - qc);
        }
        g_feat[q * DF + lane] = mv / den;
    }

    for (int xd = lane; xd < DIN; xd += 32) {
        float mv = -__int_as_float(0x7f800000);
#pragma unroll
        for (int k = 0; k < KNN; k++) {
            int j = s_nn[w][k];
            mv = fmaxf(mv, x[j * DIN + xd]);
        }
        g_feat[q * DF + 3 + xd] = mv;
    }
}

// ---------------------------------------------------------------------------
// 4) h = feat @ W + b   (tiny GEMM: 4096x67x128)
// ---------------------------------------------------------------------------
__global__ __launch_bounds__(1024)
void mlp_kernel(const float* __restrict__ W, const float* __restrict__ b)
{
    __shared__ float sW[DF * DOUT];  // 34304 B
    __shared__ float sF[8][DF];
    const int tid = threadIdx.x;
    for (int i = tid; i < DF * DOUT; i += 1024) sW[i] = W[i];
    const int qb = blockIdx.x * 8;
    for (int i = tid; i < 8 * DF; i += 1024) {
        int qq = i / DF, f = i - qq * DF;
        sF[qq][f] = g_feat[(qb + qq) * DF + f];
    }
    __syncthreads();
    const int od = tid & 127;
    const int qi = tid >> 7;
    float acc = b[od];
#pragma unroll
    for (int f = 0; f < DF; f++) acc += sF[qi][f] * sW[f * DOUT + od];
    g_h[(qb + qi) * DOUT + od] = acc;
}

// ---------------------------------------------------------------------------
// 5) BatchNorm training stats per output column (double accumulation)
// ---------------------------------------------------------------------------
__global__ __launch_bounds__(256)
void bn_stats_kernel(const float* __restrict__ gamma, const float* __restrict__ beta)
{
    const int col = blockIdx.x;
    const int tid = threadIdx.x;
    double s = 0.0, s2 = 0.0;
    for (int q = tid; q < MPTS; q += 256) {
        float v = g_h[q * DOUT + col];
        s  += (double)v;
        s2 += (double)v * (double)v;
    }
    __shared__ double sh_s[256], sh_s2[256];
    sh_s[tid] = s; sh_s2[tid] = s2;
    __syncthreads();
    for (int off = 128; off > 0; off >>= 1) {
        if (tid < off) { sh_s[tid] += sh_s[tid + off]; sh_s2[tid] += sh_s2[tid + off]; }
        __syncthreads();
    }
    if (tid == 0) {
        double mean = sh_s[0] / (double)MPTS;
        double var  = sh_s2[0] / (double)MPTS - mean * mean;
        float inv   = (float)(1.0 / sqrt(var + 1e-5));
        float sc    = gamma[col] * inv;
        g_scale[col] = sc;
        g_shift[col] = beta[col] - (float)mean * sc;
    }
}

// ---------------------------------------------------------------------------
// 6) normalize + ReLU -> output; write n_o tail
// ---------------------------------------------------------------------------
__global__ __launch_bounds__(1024)
void finalize_kernel(float* __restrict__ out, int tail)
{
    const int idx = blockIdx.x * 1024 + threadIdx.x;
    if (idx < MPTS * DOUT) {
        const int od = idx & 127;
        float v = g_h[idx] * g_scale[od] + g_shift[od];
        out[3 * MPTS + idx] = v > 0.0f ? v : 0.0f;
    }
    if (idx == 0) {
        for (int t = 0; t < tail; t++)
            out[3 * MPTS + MPTS * DOUT + t] = (float)MPTS;  // n_o = [M]
    }
}

// ---------------------------------------------------------------------------
extern "C" void kernel_launch(void* const* d_in, const int* in_sizes, int n_in,
                              void* d_out, int out_size)
{
    const float* p     = (const float*)d_in[0];
    const float* x     = (const float*)d_in[1];
    // d_in[2] = offsets o (unused, single cloud)
    const float* W     = (const float*)d_in[3];
    const float* b     = (const float*)d_in[4];
    const float* gamma = (const float*)d_in[5];
    const float* beta  = (const float*)d_in[6];
    float* out = (float*)d_out;

    cudaFuncSetAttribute(fps_kernel, cudaFuncAttributeMaxDynamicSharedMemorySize,
                         3 * NPTS * (int)sizeof(float));

    fps_kernel<<<1, FPS_T, 3 * NPTS * sizeof(float)>>>(p, out);

    dim3 gA(MPTS / 256, NCHUNK);
    knn_kernel<<<gA, 256>>>(p, out);

    feat_kernel<<<MPTS / 4, 128>>>(p, x, out);

    mlp_kernel<<<MPTS / 8, 1024>>>(W, b);

    bn_stats_kernel<<<DOUT, 256>>>(gamma, beta);

    int tail = out_size - (3 * MPTS + MPTS * DOUT);
    if (tail < 0) tail = 0;
    finalize_kernel<<<(MPTS * DOUT + 1023) / 1024, 1024>>>(out, tail);
}

// round 5
// speedup vs baseline: 1.4775x; 1.4775x over previous
#include <cuda_runtime.h>
#include <math.h>

// Problem constants (fixed shapes)
#define NPTS   16384
#define MPTS   4096          // NPTS / STRIDE(4)
#define KNN    16
#define DIN    64
#define DF     67            // 3 + DIN
#define DOUT   128
#define NCHUNK 8
#define CHSZ   (NPTS / NCHUNK)   // 2048
#define FPS_T  1024
#define PPT    (NPTS / FPS_T)    // 16
#define NBINS  4096              // 16x16x16 Morton cells

#define F_INF  __int_as_float(0x7f800000)

// ---------------- scratch (static device allocations; no cudaMalloc) -------
__device__ float g_cand_d[MPTS * NCHUNK * KNN];
__device__ int   g_cand_i[MPTS * NCHUNK * KNN];
__device__ float g_feat[MPTS * DF];
__device__ float g_h[MPTS * DOUT];
__device__ float g_scale[DOUT];
__device__ float g_shift[DOUT];
__device__ float g_sx[NPTS];
__device__ float g_sy[NPTS];
__device__ float g_sz[NPTS];
__device__ int   g_sidx[NPTS];     // sorted position -> original index
__device__ int   g_code[NPTS];

// ---------------------------------------------------------------------------
// 0) Preprocess: bbox -> Morton cell id (16^3) -> counting sort of coords
//    (keeping original indices). Single block. The sort only changes
//    scheduling; all FPS comparisons use ORIGINAL indices so results match
//    the reference bit-for-bit, including ties.
// ---------------------------------------------------------------------------
__device__ __forceinline__ unsigned mort4(unsigned x)
{
    return (x & 1u) | ((x & 2u) << 2) | ((x & 4u) << 4) | ((x & 8u) << 6);
}

__global__ __launch_bounds__(1024, 1)
void prep_kernel(const float* __restrict__ p)
{
    __shared__ int   sh_hist[NBINS];
    __shared__ float sh_r[32][6];
    __shared__ float sh_bb[6];
    __shared__ int   sh_wt[32];

    const int tid  = threadIdx.x;
    const int lane = tid & 31;
    const int wid  = tid >> 5;

    // ---- bbox reduce ----
    float mnx = F_INF, mny = F_INF, mnz = F_INF;
    float mxx = -F_INF, mxy = -F_INF, mxz = -F_INF;
    for (int j = 0; j < PPT; j++) {
        const int i = tid + (j << 10);
        float px = p[3 * i + 0], py = p[3 * i + 1], pz = p[3 * i + 2];
        mnx = fminf(mnx, px); mxx = fmaxf(mxx, px);
        mny = fminf(mny, py); mxy = fmaxf(mxy, py);
        mnz = fminf(mnz, pz); mxz = fmaxf(mxz, pz);
    }
#pragma unroll
    for (int off = 16; off > 0; off >>= 1) {
        mnx = fminf(mnx, __shfl_xor_sync(0xffffffffu, mnx, off));
        mny = fminf(mny, __shfl_xor_sync(0xffffffffu, mny, off));
        mnz = fminf(mnz, __shfl_xor_sync(0xffffffffu, mnz, off));
        mxx = fmaxf(mxx, __shfl_xor_sync(0xffffffffu, mxx, off));
        mxy = fmaxf(mxy, __shfl_xor_sync(0xffffffffu, mxy, off));
        mxz = fmaxf(mxz, __shfl_xor_sync(0xffffffffu, mxz, off));
    }
    if (lane == 0) {
        sh_r[wid][0] = mnx; sh_r[wid][1] = mny; sh_r[wid][2] = mnz;
        sh_r[wid][3] = mxx; sh_r[wid][4] = mxy; sh_r[wid][5] = mxz;
    }
    __syncthreads();
    if (wid == 0) {
        mnx = sh_r[lane][0]; mny = sh_r[lane][1]; mnz = sh_r[lane][2];
        mxx = sh_r[lane][3]; mxy = sh_r[lane][4]; mxz = sh_r[lane][5];
#pragma unroll
        for (int off = 16; off > 0; off >>= 1) {
            mnx = fminf(mnx, __shfl_xor_sync(0xffffffffu, mnx, off));
            mny = fminf(mny, __shfl_xor_sync(0xffffffffu, mny, off));
            mnz = fminf(mnz, __shfl_xor_sync(0xffffffffu, mnz, off));
            mxx = fmaxf(mxx, __shfl_xor_sync(0xffffffffu, mxx, off));
            mxy = fmaxf(mxy, __shfl_xor_sync(0xffffffffu, mxy, off));
            mxz = fmaxf(mxz, __shfl_xor_sync(0xffffffffu, mxz, off));
        }
        if (lane == 0) {
            sh_bb[0] = mnx; sh_bb[1] = mny; sh_bb[2] = mnz;
            sh_bb[3] = mxx; sh_bb[4] = mxy; sh_bb[5] = mxz;
        }
    }
    // zero hist
    for (int i = tid; i < NBINS; i += 1024) sh_hist[i] = 0;
    __syncthreads();

    const float bx0 = sh_bb[0], by0 = sh_bb[1], bz0 = sh_bb[2];
    const float ivx = 16.0f / fmaxf(sh_bb[3] - bx0, 1e-20f);
    const float ivy = 16.0f / fmaxf(sh_bb[4] - by0, 1e-20f);
    const float ivz = 16.0f / fmaxf(sh_bb[5] - bz0, 1e-20f);

    // ---- codes + histogram ----
    for (int j = 0; j < PPT; j++) {
        const int i = tid + (j << 10);
        float px = p[3 * i + 0], py = p[3 * i + 1], pz = p[3 * i + 2];
        int cx = min(15, max(0, (int)((px - bx0) * ivx)));
        int cy = min(15, max(0, (int)((py - by0) * ivy)));
        int cz = min(15, max(0, (int)((pz - bz0) * ivz)));
        int code = (int)(mort4((unsigned)cx) | (mort4((unsigned)cy) << 1)
                         | (mort4((unsigned)cz) << 2));
        g_code[i] = code;
        atomicAdd(&sh_hist[code], 1);
    }
    __syncthreads();

    // ---- exclusive scan of 4096 bins (4 per thread) ----
    int b0 = sh_hist[4 * tid + 0];
    int b1 = sh_hist[4 * tid + 1];
    int b2 = sh_hist[4 * tid + 2];
    int b3 = sh_hist[4 * tid + 3];
    int tsum = b0 + b1 + b2 + b3;
    int v = tsum;
#pragma unroll
    for (int off = 1; off < 32; off <<= 1) {
        int n = __shfl_up_sync(0xffffffffu, v, off);
        if (lane >= off) v += n;
    }
    const int excl = v - tsum;
    if (lane == 31) sh_wt[wid] = v;
    __syncthreads();
    if (wid == 0) {
        int wv = sh_wt[lane];
        int sv = wv;
#pragma unroll
        for (int off = 1; off < 32; off <<= 1) {
            int n = __shfl_up_sync(0xffffffffu, sv, off);
            if (lane >= off) sv += n;
        }
        sh_wt[lane] = sv - wv;  // exclusive warp offsets
    }
    __syncthreads();
    const int toff = sh_wt[wid] + excl;
    sh_hist[4 * tid + 0] = toff;
    sh_hist[4 * tid + 1] = toff + b0;
    sh_hist[4 * tid + 2] = toff + b0 + b1;
    sh_hist[4 * tid + 3] = toff + b0 + b1 + b2;
    __syncthreads();

    // ---- scatter sorted coords + original indices ----
    for (int j = 0; j < PPT; j++) {
        const int i = tid + (j << 10);
        const int code = g_code[i];
        const int pos = atomicAdd(&sh_hist[code], 1);
        g_sx[pos] = p[3 * i + 0];
        g_sy[pos] = p[3 * i + 1];
        g_sz[pos] = p[3 * i + 2];
        g_sidx[pos] = i;
    }
}

// ---------------------------------------------------------------------------
// 1) FPS with exact per-chunk bbox pruning. Single persistent block.
//    Each thread owns 16 consecutive Morton-sorted points: coords in smem
//    (transposed [k][tid] layout), min-dists + original ids + chunk bbox +
//    cached (maxd, orig argmax, sorted argmax) in registers. Skip when the
//    bbox lower-bound dist^2 provably exceeds the chunk's max min-dist ->
//    d-evolution identical to brute force. ALL tie-breaks use ORIGINAL
//    indices (jnp.argmax first-occurrence semantics). Exact non-FMA
//    distance math matches the reference rounding.
// ---------------------------------------------------------------------------
__global__ __launch_bounds__(FPS_T, 1)
void fps_kernel(const float* __restrict__ p, float* __restrict__ np_out)
{
    extern __shared__ float sm[];
    float* sxT = sm;                 // [16][1024]
    float* syT = sm + NPTS;
    float* szT = sm + 2 * NPTS;
    __shared__ float red_v[32];
    __shared__ int   red_o[32];
    __shared__ int   red_s[32];
    __shared__ float cur[3];

    const int tid  = threadIdx.x;
    const int lane = tid & 31;
    const int wid  = tid >> 5;

    // load sorted coords, transposed: sorted index i -> [(i&15)][i>>4]
    for (int j = 0; j < PPT; j++) {
        const int i = tid + (j << 10);
        const int col = ((i & 15) << 10) | (i >> 4);
        sxT[col] = g_sx[i];
        syT[col] = g_sy[i];
        szT[col] = g_sz[i];
    }

    // original index of each owned point (chunk = sorted [16*tid, 16*tid+15])
    int oid[PPT];
#pragma unroll
    for (int k = 0; k < PPT; k++) oid[k] = g_sidx[(tid << 4) | k];

    if (tid == 0) {
        cur[0] = p[0]; cur[1] = p[1]; cur[2] = p[2];
        np_out[0] = p[0]; np_out[1] = p[1]; np_out[2] = p[2];
    }
    __syncthreads();

    // chunk bbox (registers)
    float bxl = F_INF, byl = F_INF, bzl = F_INF;
    float bxh = -F_INF, byh = -F_INF, bzh = -F_INF;
#pragma unroll
    for (int k = 0; k < PPT; k++) {
        const int col = (k << 10) | tid;
        float x = sxT[col], y = syT[col], z = szT[col];
        bxl = fminf(bxl, x); bxh = fmaxf(bxh, x);
        byl = fminf(byl, y); byh = fmaxf(byh, y);
        bzl = fminf(bzl, z); bzh = fmaxf(bzh, z);
    }

    float d[PPT];
#pragma unroll
    for (int k = 0; k < PPT; k++) d[k] = F_INF;
    float my_v = -1.0f;          // cached chunk max min-dist
    int   my_o = 0x7fffffff;     // cached argmax, ORIGINAL index
    int   my_s = tid << 4;       // cached argmax, sorted index (coord lookup)
    // (it=1 always updates every chunk: lb < inf)

    for (int it = 1; it < MPTS; it++) {
        const float lx = cur[0], ly = cur[1], lz = cur[2];

        // lower-bound dist^2 from sample to chunk bbox
        float ex = fmaxf(fmaxf(bxl - lx, lx - bxh), 0.0f);
        float ey = fmaxf(fmaxf(byl - ly, ly - byh), 0.0f);
        float ez = fmaxf(fmaxf(bzl - lz, lz - bzh), 0.0f);
        float lb = ex * ex + ey * ey + ez * ez;

        if (lb < my_v * 1.00002f || my_v < 0.0f) {  // safety >> lb rounding err
            float bv = -1.0f;
            int   bo = 0x7fffffff;
            int   bk = 0;
#pragma unroll
            for (int k = 0; k < PPT; k++) {
                const int col = (k << 10) | tid;
                float dx = __fsub_rn(sxT[col], lx);
                float dy = __fsub_rn(syT[col], ly);
                float dz = __fsub_rn(szT[col], lz);
                float s  = __fadd_rn(__fadd_rn(__fmul_rn(dx, dx), __fmul_rn(dy, dy)),
                                     __fmul_rn(dz, dz));
                float dn = fminf(d[k], s);
                d[k] = dn;
                if (dn > bv || (dn == bv && oid[k] < bo)) { bv = dn; bo = oid[k]; bk = k; }
            }
            my_v = bv;
            my_o = bo;
            my_s = (tid << 4) | bk;
        }

        // block argmax of (my_v, my_o), smaller ORIGINAL index on ties
        float rv = my_v;
        int   ro = my_o;
        int   rs = my_s;
#pragma unroll
        for (int off = 16; off > 0; off >>= 1) {
            float ov = __shfl_down_sync(0xffffffffu, rv, off);
            int   oo = __shfl_down_sync(0xffffffffu, ro, off);
            int   os = __shfl_down_sync(0xffffffffu, rs, off);
            if (ov > rv || (ov == rv && oo < ro)) { rv = ov; ro = oo; rs = os; }
        }
        if (lane == 0) { red_v[wid] = rv; red_o[wid] = ro; red_s[wid] = rs; }
        __syncthreads();
        if (wid == 0) {
            rv = red_v[lane];
            ro = red_o[lane];
            rs = red_s[lane];
#pragma unroll
            for (int off = 16; off > 0; off >>= 1) {
                float ov = __shfl_down_sync(0xffffffffu, rv, off);
                int   oo = __shfl_down_sync(0xffffffffu, ro, off);
                int   os = __shfl_down_sync(0xffffffffu, rs, off);
                if (ov > rv || (ov == rv && oo < ro)) { rv = ov; ro = oo; rs = os; }
            }
            if (lane == 0) {
                const int col = ((rs & 15) << 10) | (rs >> 4);
                float wx = sxT[col], wy = syT[col], wz = szT[col];
                cur[0] = wx; cur[1] = wy; cur[2] = wz;
                np_out[3 * it + 0] = wx;
                np_out[3 * it + 1] = wy;
                np_out[3 * it + 2] = wz;
            }
        }
        __syncthreads();
    }
}

// ---------------------------------------------------------------------------
// 2) kNN phase A: one thread per (query, chunk). Chunk coords staged in smem;
//    register-resident sorted top-16 with bubble insert.
// ---------------------------------------------------------------------------
__global__ __launch_bounds__(256)
void knn_kernel(const float* __restrict__ p, const float* __restrict__ np)
{
    __shared__ float sx[CHSZ], sy[CHSZ], sz[CHSZ];
    const int c = blockIdx.y;
    const int q = blockIdx.x * blockDim.x + threadIdx.x;

    for (int i = threadIdx.x; i < CHSZ; i += blockDim.x) {
        const int g = c * CHSZ + i;
        sx[i] = p[3 * g + 0];
        sy[i] = p[3 * g + 1];
        sz[i] = p[3 * g + 2];
    }
    __syncthreads();

    const float qx = np[3 * q + 0];
    const float qy = np[3 * q + 1];
    const float qz = np[3 * q + 2];

    float dk[KNN];
    int   ik[KNN];
#pragma unroll
    for (int t = 0; t < KNN; t++) { dk[t] = F_INF; ik[t] = 0; }

    for (int j = 0; j < CHSZ; j++) {
        float dx = qx - sx[j];
        float dy = qy - sy[j];
        float dz = qz - sz[j];
        float d2 = dx * dx + dy * dy + dz * dz;
        if (d2 < dk[KNN - 1]) {
            float cd = d2;
            int   ci = c * CHSZ + j;
#pragma unroll
            for (int t = 0; t < KNN; t++) {
                if (cd < dk[t]) {
                    float td = dk[t]; int ti = ik[t];
                    dk[t] = cd; ik[t] = ci;
                    cd = td; ci = ti;
                }
            }
        }
    }
    const int base = (q * NCHUNK + c) * KNN;
#pragma unroll
    for (int t = 0; t < KNN; t++) {
        g_cand_d[base + t] = dk[t];
        g_cand_i[base + t] = ik[t];
    }
}

// ---------------------------------------------------------------------------
// 3) Merge 8 sorted candidate lists -> top-16 set, gather, normalize,
//    max-pool to 67 dims. One warp per query.
// ---------------------------------------------------------------------------
__global__ __launch_bounds__(128)
void feat_kernel(const float* __restrict__ p, const float* __restrict__ x,
                 const float* __restrict__ np)
{
    const int w    = threadIdx.x >> 5;
    const int lane = threadIdx.x & 31;
    const int q    = blockIdx.x * 4 + w;

    __shared__ int s_nn[4][KNN];

    if (lane == 0) {
        int hpos[NCHUNK];
#pragma unroll
        for (int c = 0; c < NCHUNK; c++) hpos[c] = 0;
        for (int t = 0; t < KNN; t++) {
            float best = F_INF;
            int   bc   = 0;
#pragma unroll
            for (int c = 0; c < NCHUNK; c++) {
                float v = g_cand_d[(q * NCHUNK + c) * KNN + hpos[c]];
                if (v < best) { best = v; bc = c; }
            }
            s_nn[w][t] = g_cand_i[(q * NCHUNK + bc) * KNN + hpos[bc]];
            hpos[bc]++;
        }
    }
    __syncwarp();

    const float qx = np[3 * q + 0];
    const float qy = np[3 * q + 1];
    const float qz = np[3 * q + 2];

    float nr = -1.0f;
    if (lane < KNN) {
        int j = s_nn[w][lane];
        float rx = p[3 * j + 0] - qx;
        float ry = p[3 * j + 1] - qy;
        float rz = p[3 * j + 2] - qz;
        nr = sqrtf(rx * rx + ry * ry + rz * rz);
    }
#pragma unroll
    for (int off = 16; off > 0; off >>= 1)
        nr = fmaxf(nr, __shfl_xor_sync(0xffffffffu, nr, off));
    const float den = nr + 1e-8f;

    if (lane < 3) {
        const float qc = (lane == 0) ? qx : (lane == 1) ? qy : qz;
        float mv = -F_INF;
#pragma unroll
        for (int k = 0; k < KNN; k++) {
            int j = s_nn[w][k];
            mv = fmaxf(mv, p[3 * j + lane] - qc);
        }
        g_feat[q * DF + lane] = mv / den;
    }

    for (int xd = lane; xd < DIN; xd += 32) {
        float mv = -F_INF;
#pragma unroll
        for (int k = 0; k < KNN; k++) {
            int j = s_nn[w][k];
            mv = fmaxf(mv, x[j * DIN + xd]);
        }
        g_feat[q * DF + 3 + xd] = mv;
    }
}

// ---------------------------------------------------------------------------
// 4) h = feat @ W + b   (tiny GEMM: 4096x67x128)
// ---------------------------------------------------------------------------
__global__ __launch_bounds__(1024)
void mlp_kernel(const float* __restrict__ W, const float* __restrict__ b)
{
    __shared__ float sW[DF * DOUT];
    __shared__ float sF[8][DF];
    const int tid = threadIdx.x;
    for (int i = tid; i < DF * DOUT; i += 1024) sW[i] = W[i];
    const int qb = blockIdx.x * 8;
    for (int i = tid; i < 8 * DF; i += 1024) {
        int qq = i / DF, f = i - qq * DF;
        sF[qq][f] = g_feat[(qb + qq) * DF + f];
    }
    __syncthreads();
    const int od = tid & 127;
    const int qi = tid >> 7;
    float acc = b[od];
#pragma unroll
    for (int f = 0; f < DF; f++) acc += sF[qi][f] * sW[f * DOUT + od];
    g_h[(qb + qi) * DOUT + od] = acc;
}

// ---------------------------------------------------------------------------
// 5) BatchNorm training stats per output column (double accumulation)
// ---------------------------------------------------------------------------
__global__ __launch_bounds__(256)
void bn_stats_kernel(const float* __restrict__ gamma, const float* __restrict__ beta)
{
    const int col = blockIdx.x;
    const int tid = threadIdx.x;
    double s = 0.0, s2 = 0.0;
    for (int q = tid; q < MPTS; q += 256) {
        float v = g_h[q * DOUT + col];
        s  += (double)v;
        s2 += (double)v * (double)v;
    }
    __shared__ double sh_s[256], sh_s2[256];
    sh_s[tid] = s; sh_s2[tid] = s2;
    __syncthreads();
    for (int off = 128; off > 0; off >>= 1) {
        if (tid < off) { sh_s[tid] += sh_s[tid + off]; sh_s2[tid] += sh_s2[tid + off]; }
        __syncthreads();
    }
    if (tid == 0) {
        double mean = sh_s[0] / (double)MPTS;
        double var  = sh_s2[0] / (double)MPTS - mean * mean;
        float inv   = (float)(1.0 / sqrt(var + 1e-5));
        float sc    = gamma[col] * inv;
        g_scale[col] = sc;
        g_shift[col] = beta[col] - (float)mean * sc;
    }
}

// ---------------------------------------------------------------------------
// 6) normalize + ReLU -> output; write n_o tail
// ---------------------------------------------------------------------------
__global__ __launch_bounds__(1024)
void finalize_kernel(float* __restrict__ out, int tail)
{
    const int idx = blockIdx.x * 1024 + threadIdx.x;
    if (idx < MPTS * DOUT) {
        const int od = idx & 127;
        float v = g_h[idx] * g_scale[od] + g_shift[od];
        out[3 * MPTS + idx] = v > 0.0f ? v : 0.0f;
    }
    if (idx == 0) {
        for (int t = 0; t < tail; t++)
            out[3 * MPTS + MPTS * DOUT + t] = (float)MPTS;
    }
}

// ---------------------------------------------------------------------------
extern "C" void kernel_launch(void* const* d_in, const int* in_sizes, int n_in,
                              void* d_out, int out_size)
{
    const float* p     = (const float*)d_in[0];
    const float* x     = (const float*)d_in[1];
    // d_in[2] = offsets o (unused, single cloud)
    const float* W     = (const float*)d_in[3];
    const float* b     = (const float*)d_in[4];
    const float* gamma = (const float*)d_in[5];
    const float* beta  = (const float*)d_in[6];
    float* out = (float*)d_out;

    cudaFuncSetAttribute(fps_kernel, cudaFuncAttributeMaxDynamicSharedMemorySize,
                         3 * NPTS * (int)sizeof(float));

    prep_kernel<<<1, 1024>>>(p);

    fps_kernel<<<1, FPS_T, 3 * NPTS * sizeof(float)>>>(p, out);

    dim3 gA(MPTS / 256, NCHUNK);
    knn_kernel<<<gA, 256>>>(p, out);

    feat_kernel<<<MPTS / 4, 128>>>(p, x, out);

    mlp_kernel<<<MPTS / 8, 1024>>>(W, b);

    bn_stats_kernel<<<DOUT, 256>>>(gamma, beta);

    int tail = out_size - (3 * MPTS + MPTS * DOUT);
    if (tail < 0) tail = 0;
    finalize_kernel<<<(MPTS * DOUT + 1023) / 1024, 1024>>>(out, tail);
}